// round 2
// baseline (speedup 1.0000x reference)
#include <cuda_runtime.h>

#define B_  16
#define N_  4096
#define S_  1024
#define K_  32
#define C1  67
#define O1  64
#define O2  64
#define O3  128
#define M_TOT (B_*S_*K_)   // 524288 positions per channel for BN stats
#define R2  0.04f
#define OUT_XYZ_ELEMS (B_*S_*3)   // 49152

// ---------------- scratch (device globals; no allocation allowed) ----------------
__device__ float4 g_xyzw[B_*N_];            // x,y,z,|p|^2
__device__ float4 g_cent[B_*S_];            // centroid x,y,z,|c|^2
__device__ int    g_fps [B_*S_];
__device__ int    g_gidx[B_*S_*K_];
__device__ float  g_y1[(size_t)M_TOT*O1];   // 134MB
__device__ float  g_y2[(size_t)M_TOT*O2];   // 134MB
__device__ float  g_y3[(size_t)M_TOT*O3];   // 268MB
__device__ double g_sum[3*128];
__device__ double g_sq [3*128];
__device__ float  g_scale[3*128];
__device__ float  g_shift[3*128];

// ---------------- prep: pack xyz + |p|^2, zero stats ----------------
__global__ void prep_kernel(const float* __restrict__ xyz) {
    int i = blockIdx.x * 256 + threadIdx.x;
    if (blockIdx.x == 0) {
        // zero ALL 384 stat slots (strided: blockDim is 256)
        for (int j = threadIdx.x; j < 3*128; j += 256) {
            g_sum[j] = 0.0;
            g_sq [j] = 0.0;
        }
    }
    if (i < B_*N_) {
        float x = xyz[3*i], y = xyz[3*i+1], z = xyz[3*i+2];
        float ss = __fadd_rn(__fadd_rn(__fmul_rn(x,x), __fmul_rn(y,y)), __fmul_rn(z,z));
        g_xyzw[i] = make_float4(x, y, z, ss);
    }
}

// ---------------- FPS: one block per batch, 512 thr, 8 pts/thr ----------------
__global__ __launch_bounds__(512) void fps_kernel(float* __restrict__ out) {
    int b = blockIdx.x, tid = threadIdx.x;
    int lane = tid & 31, wid = tid >> 5;
    __shared__ float sv[2][16];
    __shared__ int   si[2][16];
    const float4* base = g_xyzw + b * N_;

    float px[8], py[8], pz[8], d[8];
#pragma unroll
    for (int j = 0; j < 8; j++) {
        float4 p = base[tid*8 + j];
        px[j] = p.x; py[j] = p.y; pz[j] = p.z; d[j] = 1e10f;
    }
    float4 c0 = base[0];
    float cx = c0.x, cy = c0.y, cz = c0.z;
    if (tid == 0) {
        g_fps[b*S_] = 0;
        float* o = out + (size_t)(b*S_)*3;
        o[0] = cx; o[1] = cy; o[2] = cz;
        float cs = __fadd_rn(__fadd_rn(__fmul_rn(cx,cx), __fmul_rn(cy,cy)), __fmul_rn(cz,cz));
        g_cent[b*S_] = make_float4(cx, cy, cz, cs);
    }
    int p = 0;
    for (int it = 1; it < S_; ++it) {
        float bestv = -1.0f; int besti = 0;
#pragma unroll
        for (int j = 0; j < 8; j++) {
            float dx = px[j] - cx, dy = py[j] - cy, dz = pz[j] - cz;
            float dd = __fadd_rn(__fadd_rn(__fmul_rn(dx,dx), __fmul_rn(dy,dy)), __fmul_rn(dz,dz));
            d[j] = fminf(d[j], dd);
            if (d[j] > bestv) { bestv = d[j]; besti = tid*8 + j; }
        }
#pragma unroll
        for (int off = 16; off; off >>= 1) {
            float ov = __shfl_down_sync(0xffffffffu, bestv, off);
            int   oi = __shfl_down_sync(0xffffffffu, besti, off);
            if (ov > bestv || (ov == bestv && oi < besti)) { bestv = ov; besti = oi; }
        }
        if (lane == 0) { sv[p][wid] = bestv; si[p][wid] = besti; }
        __syncthreads();
        float wv = sv[p][0]; int wi = si[p][0];
#pragma unroll
        for (int w = 1; w < 16; w++) {
            float v = sv[p][w]; int ii = si[p][w];
            if (v > wv || (v == wv && ii < wi)) { wv = v; wi = ii; }
        }
        float4 cc = base[wi];
        cx = cc.x; cy = cc.y; cz = cc.z;
        if (tid == 0) {
            g_fps[b*S_ + it] = wi;
            float* o = out + (size_t)(b*S_ + it)*3;
            o[0] = cx; o[1] = cy; o[2] = cz;
            float cs = __fadd_rn(__fadd_rn(__fmul_rn(cx,cx), __fmul_rn(cy,cy)), __fmul_rn(cz,cz));
            g_cent[b*S_ + it] = make_float4(cx, cy, cz, cs);
        }
        p ^= 1;
    }
}

// ---------------- ball query: one warp per centroid ----------------
__global__ __launch_bounds__(256) void ballq_kernel() {
    int m = blockIdx.x * 8 + (threadIdx.x >> 5);
    int lane = threadIdx.x & 31;
    int b = m >> 10;
    float4 c = g_cent[m];
    const float4* base = g_xyzw + b * N_;
    int* gout = g_gidx + m * K_;
    int cnt = 0, first = 0;
    for (int bn = 0; bn < N_; bn += 32) {
        int n = bn + lane;
        float4 pt = base[n];
        float dot = __fadd_rn(__fadd_rn(__fmul_rn(c.x,pt.x), __fmul_rn(c.y,pt.y)), __fmul_rn(c.z,pt.z));
        float t = __fmul_rn(-2.0f, dot);
        t = __fadd_rn(t, c.w);
        t = __fadd_rn(t, pt.w);
        bool in = (t <= R2);
        unsigned mask = __ballot_sync(0xffffffffu, in);
        if (cnt == 0 && mask) first = __shfl_sync(0xffffffffu, n, __ffs(mask) - 1);
        int pos = cnt + __popc(mask & ((1u << lane) - 1u));
        if (in && pos < K_) gout[pos] = n;
        cnt += __popc(mask);
        if (cnt >= K_) break;
    }
    for (int j = cnt + lane; j < K_; j += 32) gout[j] = first;
}

// ---------------- conv1: gather + (64x67) GEMM + bias + stats ----------------
__global__ __launch_bounds__(256) void conv1_kernel(const float* __restrict__ pts,
                                                    const float* __restrict__ w,
                                                    const float* __restrict__ bias) {
    int m = blockIdx.x, b = m >> 10, tid = threadIdx.x;
    __shared__ float ws[64*69];
    __shared__ float fs[32*68];
    __shared__ float ssum[64], ssq[64];
    for (int i = tid; i < 64*67; i += 256) { int o = i / 67, c = i - o*67; ws[o*69 + c] = w[i]; }
    if (tid < 64) { ssum[tid] = 0.f; ssq[tid] = 0.f; }
    {
        int k = tid >> 3, l = tid & 7;
        int idx = g_gidx[m*K_ + k];
        if (l == 0) {
            float4 cen = g_cent[m];
            float4 pp = g_xyzw[b*N_ + idx];
            fs[k*68 + 0] = pp.x - cen.x;
            fs[k*68 + 1] = pp.y - cen.y;
            fs[k*68 + 2] = pp.z - cen.z;
        }
        const float* prow = pts + ((size_t)(b*N_ + idx)) * 64;
        for (int c = l; c < 64; c += 8) fs[k*68 + 3 + c] = prow[c];
    }
    __syncthreads();
    int to = tid & 15, k0 = (tid >> 4) * 2;
    float acc[4][2];
#pragma unroll
    for (int i = 0; i < 4; i++) { float bv = bias[to + 16*i]; acc[i][0] = bv; acc[i][1] = bv; }
    const float* f0 = &fs[k0*68];
    const float* f1 = &fs[(k0+1)*68];
    for (int c = 0; c < 67; c++) {
        float fa = f0[c], fb = f1[c];
#pragma unroll
        for (int i = 0; i < 4; i++) {
            float wv = ws[(to + 16*i)*69 + c];
            acc[i][0] += wv * fa;
            acc[i][1] += wv * fb;
        }
    }
    float* yo = g_y1 + (size_t)m * (K_*O1);
#pragma unroll
    for (int i = 0; i < 4; i++) {
        int o = to + 16*i;
        yo[k0*O1 + o]     = acc[i][0];
        yo[(k0+1)*O1 + o] = acc[i][1];
        atomicAdd(&ssum[o], acc[i][0] + acc[i][1]);
        atomicAdd(&ssq[o],  acc[i][0]*acc[i][0] + acc[i][1]*acc[i][1]);
    }
    __syncthreads();
    if (tid < 64) {
        atomicAdd(&g_sum[tid], (double)ssum[tid]);
        atomicAdd(&g_sq [tid], (double)ssq[tid]);
    }
}

// ---------------- conv2: normrelu(y1) -> (64x64) GEMM + bias + stats ----------------
__global__ __launch_bounds__(256) void conv2_kernel(const float* __restrict__ w,
                                                    const float* __restrict__ bias) {
    int m = blockIdx.x, tid = threadIdx.x;
    __shared__ float ws[64*65];
    __shared__ float fs[32*64];
    __shared__ float ssum[64], ssq[64];
    for (int i = tid; i < 64*64; i += 256) { int o = i >> 6, c = i & 63; ws[o*65 + c] = w[i]; }
    if (tid < 64) { ssum[tid] = 0.f; ssq[tid] = 0.f; }
    const float* yin = g_y1 + (size_t)m * 2048;
    for (int i = tid; i < 2048; i += 256) {
        int c = i & 63;
        float v = yin[i] * g_scale[c] + g_shift[c];
        fs[i] = fmaxf(v, 0.f);
    }
    __syncthreads();
    int to = tid & 15, k0 = (tid >> 4) * 2;
    float acc[4][2];
#pragma unroll
    for (int i = 0; i < 4; i++) { float bv = bias[to + 16*i]; acc[i][0] = bv; acc[i][1] = bv; }
    const float* f0 = &fs[k0*64];
    const float* f1 = &fs[(k0+1)*64];
    for (int c = 0; c < 64; c++) {
        float fa = f0[c], fb = f1[c];
#pragma unroll
        for (int i = 0; i < 4; i++) {
            float wv = ws[(to + 16*i)*65 + c];
            acc[i][0] += wv * fa;
            acc[i][1] += wv * fb;
        }
    }
    float* yo = g_y2 + (size_t)m * 2048;
#pragma unroll
    for (int i = 0; i < 4; i++) {
        int o = to + 16*i;
        yo[k0*O2 + o]     = acc[i][0];
        yo[(k0+1)*O2 + o] = acc[i][1];
        atomicAdd(&ssum[o], acc[i][0] + acc[i][1]);
        atomicAdd(&ssq[o],  acc[i][0]*acc[i][0] + acc[i][1]*acc[i][1]);
    }
    __syncthreads();
    if (tid < 64) {
        atomicAdd(&g_sum[128 + tid], (double)ssum[tid]);
        atomicAdd(&g_sq [128 + tid], (double)ssq[tid]);
    }
}

// ---------------- conv3: normrelu(y2) -> (128x64) GEMM + bias + stats ----------------
__global__ __launch_bounds__(256) void conv3_kernel(const float* __restrict__ w,
                                                    const float* __restrict__ bias) {
    int m = blockIdx.x, tid = threadIdx.x;
    __shared__ float ws[128*65];   // 33280B
    __shared__ float fs[32*64];
    __shared__ float ssum[128], ssq[128];
    for (int i = tid; i < 128*64; i += 256) { int o = i >> 6, c = i & 63; ws[o*65 + c] = w[i]; }
    if (tid < 128) { ssum[tid] = 0.f; ssq[tid] = 0.f; }
    const float* yin = g_y2 + (size_t)m * 2048;
    for (int i = tid; i < 2048; i += 256) {
        int c = i & 63;
        float v = yin[i] * g_scale[128 + c] + g_shift[128 + c];
        fs[i] = fmaxf(v, 0.f);
    }
    __syncthreads();
    int to = tid & 15, k0 = (tid >> 4) * 2;
    float acc[8][2];
#pragma unroll
    for (int i = 0; i < 8; i++) { float bv = bias[to + 16*i]; acc[i][0] = bv; acc[i][1] = bv; }
    const float* f0 = &fs[k0*64];
    const float* f1 = &fs[(k0+1)*64];
    for (int c = 0; c < 64; c++) {
        float fa = f0[c], fb = f1[c];
#pragma unroll
        for (int i = 0; i < 8; i++) {
            float wv = ws[(to + 16*i)*65 + c];
            acc[i][0] += wv * fa;
            acc[i][1] += wv * fb;
        }
    }
    float* yo = g_y3 + (size_t)m * (K_*O3);
#pragma unroll
    for (int i = 0; i < 8; i++) {
        int o = to + 16*i;
        yo[k0*O3 + o]     = acc[i][0];
        yo[(k0+1)*O3 + o] = acc[i][1];
        atomicAdd(&ssum[o], acc[i][0] + acc[i][1]);
        atomicAdd(&ssq[o],  acc[i][0]*acc[i][0] + acc[i][1]*acc[i][1]);
    }
    __syncthreads();
    if (tid < 128) {
        atomicAdd(&g_sum[256 + tid], (double)ssum[tid]);
        atomicAdd(&g_sq [256 + tid], (double)ssq[tid]);
    }
}

// ---------------- BN finalize: fold mean/var + gamma/beta into scale/shift ----------------
__global__ void finalize_kernel(const float* __restrict__ g,
                                const float* __restrict__ beta,
                                int layer, int C) {
    int c = threadIdx.x;
    if (c < C) {
        double mean = g_sum[layer*128 + c] / (double)M_TOT;
        double var  = g_sq [layer*128 + c] / (double)M_TOT - mean*mean;
        float rstd = rsqrtf((float)var + 1e-5f);
        float sc = g[c] * rstd;
        g_scale[layer*128 + c] = sc;
        g_shift[layer*128 + c] = beta[c] - (float)mean * sc;
    }
}

// ---------------- maxpool over K samples (BN+relu folded: init 0) ----------------
__global__ __launch_bounds__(128) void maxpool_kernel(float* __restrict__ out) {
    int m = blockIdx.x, o = threadIdx.x;
    float sc = g_scale[256 + o], sh = g_shift[256 + o];
    const float* y = g_y3 + (size_t)m * (K_*O3);
    float mx = 0.f;   // relu lower bound
#pragma unroll 4
    for (int k = 0; k < K_; k++) {
        float v = y[k*O3 + o] * sc + sh;
        mx = fmaxf(mx, v);
    }
    out[OUT_XYZ_ELEMS + (size_t)m*O3 + o] = mx;
}

extern "C" void kernel_launch(void* const* d_in, const int* in_sizes, int n_in,
                              void* d_out, int out_size) {
    const float* xyz   = (const float*)d_in[0];
    const float* pts   = (const float*)d_in[1];
    const float* w1    = (const float*)d_in[2];
    const float* b1    = (const float*)d_in[3];
    const float* g1    = (const float*)d_in[4];
    const float* beta1 = (const float*)d_in[5];
    const float* w2    = (const float*)d_in[6];
    const float* b2    = (const float*)d_in[7];
    const float* g2    = (const float*)d_in[8];
    const float* beta2 = (const float*)d_in[9];
    const float* w3    = (const float*)d_in[10];
    const float* b3    = (const float*)d_in[11];
    const float* g3    = (const float*)d_in[12];
    const float* beta3 = (const float*)d_in[13];
    float* out = (float*)d_out;

    prep_kernel<<<(B_*N_ + 255)/256, 256>>>(xyz);
    fps_kernel<<<B_, 512>>>(out);
    ballq_kernel<<<(B_*S_)/8, 256>>>();
    conv1_kernel<<<B_*S_, 256>>>(pts, w1, b1);
    finalize_kernel<<<1, 128>>>(g1, beta1, 0, 64);
    conv2_kernel<<<B_*S_, 256>>>(w2, b2);
    finalize_kernel<<<1, 128>>>(g2, beta2, 1, 64);
    conv3_kernel<<<B_*S_, 256>>>(w3, b3);
    finalize_kernel<<<1, 128>>>(g3, beta3, 2, 128);
    maxpool_kernel<<<B_*S_, 128>>>(out);
}

// round 4
// speedup vs baseline: 1.1791x; 1.1791x over previous
#include <cuda_runtime.h>

#define B_  16
#define N_  4096
#define S_  1024
#define K_  32
#define M_TOT (B_*S_*K_)   // 524288 rows
#define R2  0.04f
#define OUT_XYZ_ELEMS (B_*S_*3)
#define NC  (B_*S_)        // 16384 centroids

// ---------------- scratch ----------------
__device__ float4 g_xyzw[B_*N_];
__device__ float4 g_cent[NC];
__device__ int    g_gidx[NC*K_];
__device__ float  g_y1[(size_t)M_TOT*64];   // 134MB
__device__ float  g_y2[(size_t)M_TOT*64];   // 134MB
__device__ float  g_mx[(size_t)NC*128];     // 8MB
__device__ float  g_mn[(size_t)NC*128];     // 8MB
__device__ float  g_wt1[68*64];             // [k][o], k=67 row zero
__device__ float  g_wt2[64*64];
__device__ float  g_wt3[64*128];
__device__ double g_sum[3*128];
__device__ double g_sq [3*128];
__device__ float  g_scale[3*128];
__device__ float  g_shift[3*128];

__device__ __forceinline__ unsigned fenc(float f) {
    int b = __float_as_int(f);
    return (b >= 0) ? ((unsigned)b | 0x80000000u) : ~(unsigned)b;
}
__device__ __forceinline__ float fdec(unsigned k) {
    int b = (k & 0x80000000u) ? (int)(k & 0x7fffffffu) : ~(int)k;
    return __int_as_float(b);
}

// ---------------- prep: pack xyz + |p|^2 ----------------
__global__ void prep_kernel(const float* __restrict__ xyz) {
    int i = blockIdx.x * 256 + threadIdx.x;
    if (i < B_*N_) {
        float x = xyz[3*i], y = xyz[3*i+1], z = xyz[3*i+2];
        float ss = __fadd_rn(__fadd_rn(__fmul_rn(x,x), __fmul_rn(y,y)), __fmul_rn(z,z));
        g_xyzw[i] = make_float4(x, y, z, ss);
    }
}

// ---------------- wprep: transpose weights, zero stats ----------------
__global__ void wprep_kernel(const float* __restrict__ w1,
                             const float* __restrict__ w2,
                             const float* __restrict__ w3) {
    int tid = blockIdx.x * 256 + threadIdx.x;
    int stride = gridDim.x * 256;
    for (int i = tid; i < 3*128; i += stride) { g_sum[i] = 0.0; g_sq[i] = 0.0; }
    for (int i = tid; i < 68*64; i += stride) {
        int k = i >> 6, o = i & 63;
        g_wt1[i] = (k < 67) ? w1[o*67 + k] : 0.f;
    }
    for (int i = tid; i < 64*64; i += stride) {
        int k = i >> 6, o = i & 63;
        g_wt2[i] = w2[o*64 + k];
    }
    for (int i = tid; i < 64*128; i += stride) {
        int k = i >> 7, o = i & 127;
        g_wt3[i] = w3[o*64 + k];
    }
}

// ---------------- FPS (unchanged; index-critical) ----------------
__global__ __launch_bounds__(512) void fps_kernel(float* __restrict__ out) {
    int b = blockIdx.x, tid = threadIdx.x;
    int lane = tid & 31, wid = tid >> 5;
    __shared__ float sv[2][16];
    __shared__ int   si[2][16];
    const float4* base = g_xyzw + b * N_;

    float px[8], py[8], pz[8], d[8];
#pragma unroll
    for (int j = 0; j < 8; j++) {
        float4 p = base[tid*8 + j];
        px[j] = p.x; py[j] = p.y; pz[j] = p.z; d[j] = 1e10f;
    }
    float4 c0 = base[0];
    float cx = c0.x, cy = c0.y, cz = c0.z;
    if (tid == 0) {
        float* o = out + (size_t)(b*S_)*3;
        o[0] = cx; o[1] = cy; o[2] = cz;
        float cs = __fadd_rn(__fadd_rn(__fmul_rn(cx,cx), __fmul_rn(cy,cy)), __fmul_rn(cz,cz));
        g_cent[b*S_] = make_float4(cx, cy, cz, cs);
    }
    int p = 0;
    for (int it = 1; it < S_; ++it) {
        float bestv = -1.0f; int besti = 0;
#pragma unroll
        for (int j = 0; j < 8; j++) {
            float dx = px[j] - cx, dy = py[j] - cy, dz = pz[j] - cz;
            float dd = __fadd_rn(__fadd_rn(__fmul_rn(dx,dx), __fmul_rn(dy,dy)), __fmul_rn(dz,dz));
            d[j] = fminf(d[j], dd);
            if (d[j] > bestv) { bestv = d[j]; besti = tid*8 + j; }
        }
#pragma unroll
        for (int off = 16; off; off >>= 1) {
            float ov = __shfl_down_sync(0xffffffffu, bestv, off);
            int   oi = __shfl_down_sync(0xffffffffu, besti, off);
            if (ov > bestv || (ov == bestv && oi < besti)) { bestv = ov; besti = oi; }
        }
        if (lane == 0) { sv[p][wid] = bestv; si[p][wid] = besti; }
        __syncthreads();
        float wv = sv[p][0]; int wi = si[p][0];
#pragma unroll
        for (int w = 1; w < 16; w++) {
            float v = sv[p][w]; int ii = si[p][w];
            if (v > wv || (v == wv && ii < wi)) { wv = v; wi = ii; }
        }
        float4 cc = base[wi];
        cx = cc.x; cy = cc.y; cz = cc.z;
        if (tid == 0) {
            float* o = out + (size_t)(b*S_ + it)*3;
            o[0] = cx; o[1] = cy; o[2] = cz;
            float cs = __fadd_rn(__fadd_rn(__fmul_rn(cx,cx), __fmul_rn(cy,cy)), __fmul_rn(cz,cz));
            g_cent[b*S_ + it] = make_float4(cx, cy, cz, cs);
        }
        p ^= 1;
    }
}

// ---------------- ball query (unchanged; index-critical) ----------------
__global__ __launch_bounds__(256) void ballq_kernel() {
    int m = blockIdx.x * 8 + (threadIdx.x >> 5);
    int lane = threadIdx.x & 31;
    int b = m >> 10;
    float4 c = g_cent[m];
    const float4* base = g_xyzw + b * N_;
    int* gout = g_gidx + m * K_;
    int cnt = 0, first = 0;
    for (int bn = 0; bn < N_; bn += 32) {
        int n = bn + lane;
        float4 pt = base[n];
        float dot = __fadd_rn(__fadd_rn(__fmul_rn(c.x,pt.x), __fmul_rn(c.y,pt.y)), __fmul_rn(c.z,pt.z));
        float t = __fmul_rn(-2.0f, dot);
        t = __fadd_rn(t, c.w);
        t = __fadd_rn(t, pt.w);
        bool in = (t <= R2);
        unsigned mask = __ballot_sync(0xffffffffu, in);
        if (cnt == 0 && mask) first = __shfl_sync(0xffffffffu, n, __ffs(mask) - 1);
        int pos = cnt + __popc(mask & ((1u << lane) - 1u));
        if (in && pos < K_) gout[pos] = n;
        cnt += __popc(mask);
        if (cnt >= K_) break;
    }
    for (int j = cnt + lane; j < K_; j += 32) gout[j] = first;
}

// ---------------- conv1: gather + 64x128x68 GEMM, 8x8 microtile ----------------
__global__ __launch_bounds__(128) void conv1_kernel(const float* __restrict__ pts,
                                                    const float* __restrict__ bias) {
    __shared__ float fs[68*128];
    __shared__ float ws[17*64];
    __shared__ float ssum[64], ssq[64];
    int blk = blockIdx.x, tid = threadIdx.x;
    if (tid < 64) { ssum[tid] = 0.f; ssq[tid] = 0.f; }

    float rw[9];
#pragma unroll
    for (int r = 0; r < 9; r++) {
        int i = r*128 + tid;
        rw[r] = (i < 17*64) ? g_wt1[i] : 0.f;
    }

    {   // gather: one sample row per thread
        int m = blk*4 + (tid >> 5);
        int ks = tid & 31;
        int b = m >> 10;
        int idx = g_gidx[m*K_ + ks];
        float4 cen = g_cent[m];
        float4 pp  = g_xyzw[b*N_ + idx];
        fs[0*128 + tid]  = pp.x - cen.x;
        fs[1*128 + tid]  = pp.y - cen.y;
        fs[2*128 + tid]  = pp.z - cen.z;
        fs[67*128 + tid] = 0.f;
        const float4* prow = (const float4*)(pts + ((size_t)(b*N_ + idx))*64);
#pragma unroll
        for (int c4 = 0; c4 < 16; c4++) {
            float4 v = prow[c4];
            int c = 3 + c4*4;
            fs[(c+0)*128 + tid] = v.x;
            fs[(c+1)*128 + tid] = v.y;
            fs[(c+2)*128 + tid] = v.z;
            fs[(c+3)*128 + tid] = v.w;
        }
    }

    int ty = tid & 7, tx = tid >> 3;
    int o0 = ty*8, n0 = tx*8;
    float acc[8][8];
#pragma unroll
    for (int i = 0; i < 8; i++) {
        float bv = bias[o0 + i];
#pragma unroll
        for (int j = 0; j < 8; j++) acc[i][j] = bv;
    }
    __syncthreads();

    for (int kc = 0; kc < 4; kc++) {
#pragma unroll
        for (int r = 0; r < 9; r++) {
            int i = r*128 + tid;
            if (i < 17*64) ws[i] = rw[r];
        }
        __syncthreads();
        if (kc < 3) {
#pragma unroll
            for (int r = 0; r < 9; r++) {
                int i = r*128 + tid;
                rw[r] = (i < 17*64) ? g_wt1[(kc+1)*17*64 + i] : 0.f;
            }
        }
#pragma unroll
        for (int kk = 0; kk < 17; kk++) {
            const float4* ap = (const float4*)&ws[kk*64 + o0];
            const float4* bp = (const float4*)&fs[(kc*17 + kk)*128 + n0];
            float4 a0 = ap[0], a1 = ap[1];
            float4 b0 = bp[0], b1 = bp[1];
            float a[8] = {a0.x,a0.y,a0.z,a0.w,a1.x,a1.y,a1.z,a1.w};
            float b[8] = {b0.x,b0.y,b0.z,b0.w,b1.x,b1.y,b1.z,b1.w};
#pragma unroll
            for (int i = 0; i < 8; i++)
#pragma unroll
                for (int j = 0; j < 8; j++)
                    acc[i][j] += a[i]*b[j];
        }
        __syncthreads();
    }

    size_t rowbase = (size_t)blk*128;
#pragma unroll
    for (int j = 0; j < 8; j++) {
        float* yp = g_y1 + (rowbase + n0 + j)*64 + o0;
        *(float4*)yp       = make_float4(acc[0][j], acc[1][j], acc[2][j], acc[3][j]);
        *(float4*)(yp + 4) = make_float4(acc[4][j], acc[5][j], acc[6][j], acc[7][j]);
    }
#pragma unroll
    for (int i = 0; i < 8; i++) {
        float s = 0.f, q = 0.f;
#pragma unroll
        for (int j = 0; j < 8; j++) { s += acc[i][j]; q += acc[i][j]*acc[i][j]; }
        atomicAdd(&ssum[o0+i], s);
        atomicAdd(&ssq [o0+i], q);
    }
    __syncthreads();
    if (tid < 64) {
        atomicAdd(&g_sum[tid], (double)ssum[tid]);
        atomicAdd(&g_sq [tid], (double)ssq[tid]);
    }
}

// ---------------- conv2: bnrelu(y1) -> 64x128x64 GEMM ----------------
__global__ __launch_bounds__(128) void conv2_kernel(const float* __restrict__ bias) {
    __shared__ float fs[64*128];
    __shared__ float ws[16*64];
    __shared__ float scs[64], shs[64];
    __shared__ float ssum[64], ssq[64];
    int blk = blockIdx.x, tid = threadIdx.x;
    if (tid < 64) {
        scs[tid] = g_scale[tid]; shs[tid] = g_shift[tid];
        ssum[tid] = 0.f; ssq[tid] = 0.f;
    }
    float rw[8];
#pragma unroll
    for (int r = 0; r < 8; r++) rw[r] = g_wt2[r*128 + tid];
    __syncthreads();   // scs ready
    {
        const float4* yp = (const float4*)(g_y1 + ((size_t)blk*128 + tid)*64);
#pragma unroll
        for (int c4 = 0; c4 < 16; c4++) {
            float4 v = yp[c4];
            int c = c4*4;
            fs[(c+0)*128+tid] = fmaxf(v.x*scs[c+0]+shs[c+0], 0.f);
            fs[(c+1)*128+tid] = fmaxf(v.y*scs[c+1]+shs[c+1], 0.f);
            fs[(c+2)*128+tid] = fmaxf(v.z*scs[c+2]+shs[c+2], 0.f);
            fs[(c+3)*128+tid] = fmaxf(v.w*scs[c+3]+shs[c+3], 0.f);
        }
    }
    int ty = tid & 7, tx = tid >> 3;
    int o0 = ty*8, n0 = tx*8;
    float acc[8][8];
#pragma unroll
    for (int i = 0; i < 8; i++) {
        float bv = bias[o0 + i];
#pragma unroll
        for (int j = 0; j < 8; j++) acc[i][j] = bv;
    }
    __syncthreads();

    for (int kc = 0; kc < 4; kc++) {
#pragma unroll
        for (int r = 0; r < 8; r++) ws[r*128 + tid] = rw[r];
        __syncthreads();
        if (kc < 3) {
#pragma unroll
            for (int r = 0; r < 8; r++) rw[r] = g_wt2[(kc+1)*1024 + r*128 + tid];
        }
#pragma unroll
        for (int kk = 0; kk < 16; kk++) {
            const float4* ap = (const float4*)&ws[kk*64 + o0];
            const float4* bp = (const float4*)&fs[(kc*16 + kk)*128 + n0];
            float4 a0 = ap[0], a1 = ap[1];
            float4 b0 = bp[0], b1 = bp[1];
            float a[8] = {a0.x,a0.y,a0.z,a0.w,a1.x,a1.y,a1.z,a1.w};
            float b[8] = {b0.x,b0.y,b0.z,b0.w,b1.x,b1.y,b1.z,b1.w};
#pragma unroll
            for (int i = 0; i < 8; i++)
#pragma unroll
                for (int j = 0; j < 8; j++)
                    acc[i][j] += a[i]*b[j];
        }
        __syncthreads();
    }

    size_t rowbase = (size_t)blk*128;
#pragma unroll
    for (int j = 0; j < 8; j++) {
        float* yp = g_y2 + (rowbase + n0 + j)*64 + o0;
        *(float4*)yp       = make_float4(acc[0][j], acc[1][j], acc[2][j], acc[3][j]);
        *(float4*)(yp + 4) = make_float4(acc[4][j], acc[5][j], acc[6][j], acc[7][j]);
    }
#pragma unroll
    for (int i = 0; i < 8; i++) {
        float s = 0.f, q = 0.f;
#pragma unroll
        for (int j = 0; j < 8; j++) { s += acc[i][j]; q += acc[i][j]*acc[i][j]; }
        atomicAdd(&ssum[o0+i], s);
        atomicAdd(&ssq [o0+i], q);
    }
    __syncthreads();
    if (tid < 64) {
        atomicAdd(&g_sum[128 + tid], (double)ssum[tid]);
        atomicAdd(&g_sq [128 + tid], (double)ssq[tid]);
    }
}

// ---------------- conv3: bnrelu(y2) -> 128x128x64 GEMM + per-centroid max/min ----------------
__global__ __launch_bounds__(256) void conv3_kernel(const float* __restrict__ bias) {
    __shared__ float fs[64*128];
    __shared__ float ws[16*128];
    __shared__ float scs[64], shs[64];
    __shared__ float ssum[128], ssq[128];
    __shared__ unsigned smx[4*128], smn[4*128];
    int blk = blockIdx.x, tid = threadIdx.x;
    if (tid < 64) { scs[tid] = g_scale[128+tid]; shs[tid] = g_shift[128+tid]; }
    if (tid < 128) { ssum[tid] = 0.f; ssq[tid] = 0.f; }
#pragma unroll
    for (int r = 0; r < 2; r++) { smx[r*256+tid] = 0u; smn[r*256+tid] = 0xFFFFFFFFu; }
    float rw[8];
#pragma unroll
    for (int r = 0; r < 8; r++) rw[r] = g_wt3[r*256 + tid];
    __syncthreads();
    {
        int n = tid & 127, half = (tid >> 7) * 32;
        const float4* yp = (const float4*)(g_y2 + ((size_t)blk*128 + n)*64 + half);
#pragma unroll
        for (int c4 = 0; c4 < 8; c4++) {
            float4 v = yp[c4];
            int c = half + c4*4;
            fs[(c+0)*128+n] = fmaxf(v.x*scs[c+0]+shs[c+0], 0.f);
            fs[(c+1)*128+n] = fmaxf(v.y*scs[c+1]+shs[c+1], 0.f);
            fs[(c+2)*128+n] = fmaxf(v.z*scs[c+2]+shs[c+2], 0.f);
            fs[(c+3)*128+n] = fmaxf(v.w*scs[c+3]+shs[c+3], 0.f);
        }
    }
    int ty = tid & 15, tx = tid >> 4;
    int o0 = ty*8, n0 = tx*8;
    float acc[8][8];
#pragma unroll
    for (int i = 0; i < 8; i++) {
        float bv = bias[o0 + i];
#pragma unroll
        for (int j = 0; j < 8; j++) acc[i][j] = bv;
    }
    __syncthreads();

    for (int kc = 0; kc < 4; kc++) {
#pragma unroll
        for (int r = 0; r < 8; r++) ws[r*256 + tid] = rw[r];
        __syncthreads();
        if (kc < 3) {
#pragma unroll
            for (int r = 0; r < 8; r++) rw[r] = g_wt3[(kc+1)*2048 + r*256 + tid];
        }
#pragma unroll
        for (int kk = 0; kk < 16; kk++) {
            const float4* ap = (const float4*)&ws[kk*128 + o0];
            const float4* bp = (const float4*)&fs[(kc*16 + kk)*128 + n0];
            float4 a0 = ap[0], a1 = ap[1];
            float4 b0 = bp[0], b1 = bp[1];
            float a[8] = {a0.x,a0.y,a0.z,a0.w,a1.x,a1.y,a1.z,a1.w};
            float b[8] = {b0.x,b0.y,b0.z,b0.w,b1.x,b1.y,b1.z,b1.w};
#pragma unroll
            for (int i = 0; i < 8; i++)
#pragma unroll
                for (int j = 0; j < 8; j++)
                    acc[i][j] += a[i]*b[j];
        }
        __syncthreads();
    }

    int cent = tx >> 2;   // thread's 8 samples live in one centroid
#pragma unroll
    for (int i = 0; i < 8; i++) {
        float s = 0.f, q = 0.f, mx = -3.4e38f, mn = 3.4e38f;
#pragma unroll
        for (int j = 0; j < 8; j++) {
            float v = acc[i][j];
            s += v; q += v*v; mx = fmaxf(mx, v); mn = fminf(mn, v);
        }
        atomicAdd(&ssum[o0+i], s);
        atomicAdd(&ssq [o0+i], q);
        atomicMax(&smx[cent*128 + o0+i], fenc(mx));
        atomicMin(&smn[cent*128 + o0+i], fenc(mn));
    }
    __syncthreads();
    if (tid < 128) {
        atomicAdd(&g_sum[256 + tid], (double)ssum[tid]);
        atomicAdd(&g_sq [256 + tid], (double)ssq[tid]);
    }
#pragma unroll
    for (int r = 0; r < 2; r++) {
        int i = r*256 + tid;
        int c = i >> 7, o = i & 127;
        size_t gi = ((size_t)(blk*4 + c))*128 + o;
        g_mx[gi] = fdec(smx[i]);
        g_mn[gi] = fdec(smn[i]);
    }
}

// ---------------- BN finalize ----------------
__global__ void finalize_kernel(const float* __restrict__ g,
                                const float* __restrict__ beta,
                                int layer, int C) {
    int c = threadIdx.x;
    if (c < C) {
        double mean = g_sum[layer*128 + c] / (double)M_TOT;
        double var  = g_sq [layer*128 + c] / (double)M_TOT - mean*mean;
        float rstd = rsqrtf((float)var + 1e-5f);
        float sc = g[c] * rstd;
        g_scale[layer*128 + c] = sc;
        g_shift[layer*128 + c] = beta[c] - (float)mean * sc;
    }
}

// ---------------- final: BN3 fold + relu + (pre-reduced) max ----------------
__global__ __launch_bounds__(128) void final_kernel(float* __restrict__ out) {
    int m = blockIdx.x, o = threadIdx.x;
    float sc = g_scale[256 + o], sh = g_shift[256 + o];
    size_t gi = (size_t)m*128 + o;
    float y = (sc >= 0.f) ? g_mx[gi] : g_mn[gi];
    out[OUT_XYZ_ELEMS + gi] = fmaxf(y*sc + sh, 0.f);
}

extern "C" void kernel_launch(void* const* d_in, const int* in_sizes, int n_in,
                              void* d_out, int out_size) {
    const float* xyz   = (const float*)d_in[0];
    const float* pts   = (const float*)d_in[1];
    const float* w1    = (const float*)d_in[2];
    const float* b1    = (const float*)d_in[3];
    const float* g1    = (const float*)d_in[4];
    const float* beta1 = (const float*)d_in[5];
    const float* w2    = (const float*)d_in[6];
    const float* b2    = (const float*)d_in[7];
    const float* g2    = (const float*)d_in[8];
    const float* beta2 = (const float*)d_in[9];
    const float* w3    = (const float*)d_in[10];
    const float* b3    = (const float*)d_in[11];
    const float* g3    = (const float*)d_in[12];
    const float* beta3 = (const float*)d_in[13];
    float* out = (float*)d_out;

    prep_kernel<<<(B_*N_ + 255)/256, 256>>>(xyz);
    wprep_kernel<<<32, 256>>>(w1, w2, w3);
    fps_kernel<<<B_, 512>>>(out);
    ballq_kernel<<<(B_*S_)/8, 256>>>();
    conv1_kernel<<<NC/4, 128>>>(pts, b1);
    finalize_kernel<<<1, 128>>>(g1, beta1, 0, 64);
    conv2_kernel<<<NC/4, 128>>>(b2);
    finalize_kernel<<<1, 128>>>(g2, beta2, 1, 64);
    conv3_kernel<<<NC/4, 256>>>(b3);
    finalize_kernel<<<1, 128>>>(g3, beta3, 2, 128);
    final_kernel<<<NC, 128>>>(out);
}

// round 5
// speedup vs baseline: 1.5983x; 1.3555x over previous
#include <cuda_runtime.h>

#define B_  16
#define N_  4096
#define S_  1024
#define K_  32
#define M_TOT (B_*S_*K_)   // 524288 rows
#define R2  0.04f
#define OUT_XYZ_ELEMS (B_*S_*3)
#define NC  (B_*S_)        // 16384 centroids

// ---------------- scratch ----------------
__device__ float4 g_xyzw[B_*N_];
__device__ float4 g_cent[NC];
__device__ int    g_gidx[NC*K_];
__device__ float  g_y1[(size_t)M_TOT*64];   // 134MB
__device__ float  g_y2[(size_t)M_TOT*64];   // 134MB
__device__ float  g_mx[(size_t)NC*128];     // 8MB
__device__ float  g_mn[(size_t)NC*128];     // 8MB
__device__ float  g_wt1[68*64];             // [k][o], k=67 row zero
__device__ float  g_wt2[64*64];
__device__ float  g_wt3[64*128];
__device__ double g_sum[3*128];
__device__ double g_sq [3*128];
__device__ float  g_scale[3*128];
__device__ float  g_shift[3*128];

__device__ __forceinline__ unsigned fenc(float f) {
    int b = __float_as_int(f);
    return (b >= 0) ? ((unsigned)b | 0x80000000u) : ~(unsigned)b;
}
__device__ __forceinline__ float fdec(unsigned k) {
    int b = (k & 0x80000000u) ? (int)(k & 0x7fffffffu) : ~(int)k;
    return __int_as_float(b);
}

// ---------------- prep: pack xyz + |p|^2 ----------------
__global__ void prep_kernel(const float* __restrict__ xyz) {
    int i = blockIdx.x * 256 + threadIdx.x;
    if (i < B_*N_) {
        float x = xyz[3*i], y = xyz[3*i+1], z = xyz[3*i+2];
        float ss = __fadd_rn(__fadd_rn(__fmul_rn(x,x), __fmul_rn(y,y)), __fmul_rn(z,z));
        g_xyzw[i] = make_float4(x, y, z, ss);
    }
}

// ---------------- wprep: transpose weights, zero stats ----------------
__global__ void wprep_kernel(const float* __restrict__ w1,
                             const float* __restrict__ w2,
                             const float* __restrict__ w3) {
    int tid = blockIdx.x * 256 + threadIdx.x;
    int stride = gridDim.x * 256;
    for (int i = tid; i < 3*128; i += stride) { g_sum[i] = 0.0; g_sq[i] = 0.0; }
    for (int i = tid; i < 68*64; i += stride) {
        int k = i >> 6, o = i & 63;
        g_wt1[i] = (k < 67) ? w1[o*67 + k] : 0.f;
    }
    for (int i = tid; i < 64*64; i += stride) {
        int k = i >> 6, o = i & 63;
        g_wt2[i] = w2[o*64 + k];
    }
    for (int i = tid; i < 64*128; i += stride) {
        int k = i >> 7, o = i & 127;
        g_wt3[i] = w3[o*64 + k];
    }
}

// ---------------- FPS: 256 thr x 16 pts, redux-based argmax ----------------
__global__ __launch_bounds__(256) void fps_kernel(float* __restrict__ out) {
    int b = blockIdx.x, tid = threadIdx.x;
    int lane = tid & 31, wid = tid >> 5;
    __shared__ unsigned svu[2][8];
    __shared__ unsigned siu[2][8];
    const float4* base = g_xyzw + b * N_;

    float px[16], py[16], pz[16], d[16];
#pragma unroll
    for (int j = 0; j < 16; j++) {
        float4 p = base[tid*16 + j];
        px[j] = p.x; py[j] = p.y; pz[j] = p.z; d[j] = 1e10f;
    }
    float4 c0 = base[0];
    float cx = c0.x, cy = c0.y, cz = c0.z;
    if (tid == 0) {
        float* o = out + (size_t)(b*S_)*3;
        o[0] = cx; o[1] = cy; o[2] = cz;
        float cs = __fadd_rn(__fadd_rn(__fmul_rn(cx,cx), __fmul_rn(cy,cy)), __fmul_rn(cz,cz));
        g_cent[b*S_] = make_float4(cx, cy, cz, cs);
    }
    int p = 0;
    for (int it = 1; it < S_; ++it) {
        float bestv = -1.0f; int besti = 0;
#pragma unroll
        for (int j = 0; j < 16; j++) {
            float dx = px[j] - cx, dy = py[j] - cy, dz = pz[j] - cz;
            float dd = __fadd_rn(__fadd_rn(__fmul_rn(dx,dx), __fmul_rn(dy,dy)), __fmul_rn(dz,dz));
            d[j] = fminf(d[j], dd);
            if (d[j] > bestv) { bestv = d[j]; besti = tid*16 + j; }
        }
        // warp argmax: d >= 0 so float bits order == uint order
        unsigned vb = __float_as_uint(bestv);
        unsigned mx = __reduce_max_sync(0xffffffffu, vb);
        unsigned ib = (vb == mx) ? (unsigned)besti : 0xffffffffu;
        unsigned im = __reduce_min_sync(0xffffffffu, ib);
        if (lane == 0) { svu[p][wid] = mx; siu[p][wid] = im; }
        __syncthreads();
        unsigned wv = svu[p][0], wi = siu[p][0];
#pragma unroll
        for (int w = 1; w < 8; w++) {
            unsigned v = svu[p][w], ii = siu[p][w];
            if (v > wv || (v == wv && ii < wi)) { wv = v; wi = ii; }
        }
        float4 cc = base[wi];
        cx = cc.x; cy = cc.y; cz = cc.z;
        if (tid == 0) {
            float* o = out + (size_t)(b*S_ + it)*3;
            o[0] = cx; o[1] = cy; o[2] = cz;
            float cs = __fadd_rn(__fadd_rn(__fmul_rn(cx,cx), __fmul_rn(cy,cy)), __fmul_rn(cz,cz));
            g_cent[b*S_ + it] = make_float4(cx, cy, cz, cs);
        }
        p ^= 1;
    }
}

// ---------------- ball query: thread-per-centroid, smem-staged chunks ----------------
__global__ __launch_bounds__(128) void ballq_kernel() {
    __shared__ float4 ch[1024];   // 16KB chunk
    int bb = blockIdx.x, tid = threadIdx.x;
    int m = bb*128 + tid;
    int b = m >> 10;
    float4 c = g_cent[m];
    const float4* base = g_xyzw + b * N_;
    int* gout = g_gidx + m * K_;
    int cnt = 0, first = 0;
    for (int c0 = 0; c0 < N_; c0 += 1024) {
#pragma unroll
        for (int r = 0; r < 8; r++) ch[tid + r*128] = base[c0 + tid + r*128];
        __syncthreads();
        if (!__all_sync(0xffffffffu, cnt >= K_)) {
#pragma unroll 4
            for (int j = 0; j < 1024; j++) {
                float4 pt = ch[j];
                float dot = __fadd_rn(__fadd_rn(__fmul_rn(c.x,pt.x), __fmul_rn(c.y,pt.y)), __fmul_rn(c.z,pt.z));
                float t = __fmul_rn(-2.0f, dot);
                t = __fadd_rn(t, c.w);
                t = __fadd_rn(t, pt.w);
                if (t <= R2 && cnt < K_) {
                    int n = c0 + j;
                    if (cnt == 0) first = n;
                    gout[cnt] = n;
                    cnt++;
                }
            }
        }
        if (__syncthreads_and(cnt >= K_)) break;
    }
    for (int j = cnt; j < K_; j++) gout[j] = first;
}

// ---------------- conv1: gather + 64x128x68 GEMM, 8x8 microtile ----------------
__global__ __launch_bounds__(128) void conv1_kernel(const float* __restrict__ pts,
                                                    const float* __restrict__ bias) {
    __shared__ float fs[68*128];
    __shared__ float ws[17*64];
    __shared__ float ssum[64], ssq[64];
    int blk = blockIdx.x, tid = threadIdx.x;
    if (tid < 64) { ssum[tid] = 0.f; ssq[tid] = 0.f; }

    float rw[9];
#pragma unroll
    for (int r = 0; r < 9; r++) {
        int i = r*128 + tid;
        rw[r] = (i < 17*64) ? g_wt1[i] : 0.f;
    }

    {   // gather: one sample row per thread
        int m = blk*4 + (tid >> 5);
        int ks = tid & 31;
        int b = m >> 10;
        int idx = g_gidx[m*K_ + ks];
        float4 cen = g_cent[m];
        float4 pp  = g_xyzw[b*N_ + idx];
        fs[0*128 + tid]  = pp.x - cen.x;
        fs[1*128 + tid]  = pp.y - cen.y;
        fs[2*128 + tid]  = pp.z - cen.z;
        fs[67*128 + tid] = 0.f;
        const float4* prow = (const float4*)(pts + ((size_t)(b*N_ + idx))*64);
#pragma unroll
        for (int c4 = 0; c4 < 16; c4++) {
            float4 v = prow[c4];
            int c = 3 + c4*4;
            fs[(c+0)*128 + tid] = v.x;
            fs[(c+1)*128 + tid] = v.y;
            fs[(c+2)*128 + tid] = v.z;
            fs[(c+3)*128 + tid] = v.w;
        }
    }

    int ty = tid & 7, tx = tid >> 3;
    int o0 = ty*8, n0 = tx*8;
    float acc[8][8];
#pragma unroll
    for (int i = 0; i < 8; i++) {
        float bv = bias[o0 + i];
#pragma unroll
        for (int j = 0; j < 8; j++) acc[i][j] = bv;
    }
    __syncthreads();

    for (int kc = 0; kc < 4; kc++) {
#pragma unroll
        for (int r = 0; r < 9; r++) {
            int i = r*128 + tid;
            if (i < 17*64) ws[i] = rw[r];
        }
        __syncthreads();
        if (kc < 3) {
#pragma unroll
            for (int r = 0; r < 9; r++) {
                int i = r*128 + tid;
                rw[r] = (i < 17*64) ? g_wt1[(kc+1)*17*64 + i] : 0.f;
            }
        }
#pragma unroll
        for (int kk = 0; kk < 17; kk++) {
            const float4* ap = (const float4*)&ws[kk*64 + o0];
            const float4* bp = (const float4*)&fs[(kc*17 + kk)*128 + n0];
            float4 a0 = ap[0], a1 = ap[1];
            float4 b0 = bp[0], b1 = bp[1];
            float a[8] = {a0.x,a0.y,a0.z,a0.w,a1.x,a1.y,a1.z,a1.w};
            float b[8] = {b0.x,b0.y,b0.z,b0.w,b1.x,b1.y,b1.z,b1.w};
#pragma unroll
            for (int i = 0; i < 8; i++)
#pragma unroll
                for (int j = 0; j < 8; j++)
                    acc[i][j] += a[i]*b[j];
        }
        __syncthreads();
    }

    size_t rowbase = (size_t)blk*128;
#pragma unroll
    for (int j = 0; j < 8; j++) {
        float* yp = g_y1 + (rowbase + n0 + j)*64 + o0;
        *(float4*)yp       = make_float4(acc[0][j], acc[1][j], acc[2][j], acc[3][j]);
        *(float4*)(yp + 4) = make_float4(acc[4][j], acc[5][j], acc[6][j], acc[7][j]);
    }
#pragma unroll
    for (int i = 0; i < 8; i++) {
        float s = 0.f, q = 0.f;
#pragma unroll
        for (int j = 0; j < 8; j++) { s += acc[i][j]; q += acc[i][j]*acc[i][j]; }
        atomicAdd(&ssum[o0+i], s);
        atomicAdd(&ssq [o0+i], q);
    }
    __syncthreads();
    if (tid < 64) {
        atomicAdd(&g_sum[tid], (double)ssum[tid]);
        atomicAdd(&g_sq [tid], (double)ssq[tid]);
    }
}

// ---------------- conv2: bnrelu(y1) -> 64x128x64 GEMM ----------------
__global__ __launch_bounds__(128) void conv2_kernel(const float* __restrict__ bias) {
    __shared__ float fs[64*128];
    __shared__ float ws[16*64];
    __shared__ float scs[64], shs[64];
    __shared__ float ssum[64], ssq[64];
    int blk = blockIdx.x, tid = threadIdx.x;
    if (tid < 64) {
        scs[tid] = g_scale[tid]; shs[tid] = g_shift[tid];
        ssum[tid] = 0.f; ssq[tid] = 0.f;
    }
    float rw[8];
#pragma unroll
    for (int r = 0; r < 8; r++) rw[r] = g_wt2[r*128 + tid];
    __syncthreads();   // scs ready
    {
        const float4* yp = (const float4*)(g_y1 + ((size_t)blk*128 + tid)*64);
#pragma unroll
        for (int c4 = 0; c4 < 16; c4++) {
            float4 v = yp[c4];
            int c = c4*4;
            fs[(c+0)*128+tid] = fmaxf(v.x*scs[c+0]+shs[c+0], 0.f);
            fs[(c+1)*128+tid] = fmaxf(v.y*scs[c+1]+shs[c+1], 0.f);
            fs[(c+2)*128+tid] = fmaxf(v.z*scs[c+2]+shs[c+2], 0.f);
            fs[(c+3)*128+tid] = fmaxf(v.w*scs[c+3]+shs[c+3], 0.f);
        }
    }
    int ty = tid & 7, tx = tid >> 3;
    int o0 = ty*8, n0 = tx*8;
    float acc[8][8];
#pragma unroll
    for (int i = 0; i < 8; i++) {
        float bv = bias[o0 + i];
#pragma unroll
        for (int j = 0; j < 8; j++) acc[i][j] = bv;
    }
    __syncthreads();

    for (int kc = 0; kc < 4; kc++) {
#pragma unroll
        for (int r = 0; r < 8; r++) ws[r*128 + tid] = rw[r];
        __syncthreads();
        if (kc < 3) {
#pragma unroll
            for (int r = 0; r < 8; r++) rw[r] = g_wt2[(kc+1)*1024 + r*128 + tid];
        }
#pragma unroll
        for (int kk = 0; kk < 16; kk++) {
            const float4* ap = (const float4*)&ws[kk*64 + o0];
            const float4* bp = (const float4*)&fs[(kc*16 + kk)*128 + n0];
            float4 a0 = ap[0], a1 = ap[1];
            float4 b0 = bp[0], b1 = bp[1];
            float a[8] = {a0.x,a0.y,a0.z,a0.w,a1.x,a1.y,a1.z,a1.w};
            float b[8] = {b0.x,b0.y,b0.z,b0.w,b1.x,b1.y,b1.z,b1.w};
#pragma unroll
            for (int i = 0; i < 8; i++)
#pragma unroll
                for (int j = 0; j < 8; j++)
                    acc[i][j] += a[i]*b[j];
        }
        __syncthreads();
    }

    size_t rowbase = (size_t)blk*128;
#pragma unroll
    for (int j = 0; j < 8; j++) {
        float* yp = g_y2 + (rowbase + n0 + j)*64 + o0;
        *(float4*)yp       = make_float4(acc[0][j], acc[1][j], acc[2][j], acc[3][j]);
        *(float4*)(yp + 4) = make_float4(acc[4][j], acc[5][j], acc[6][j], acc[7][j]);
    }
#pragma unroll
    for (int i = 0; i < 8; i++) {
        float s = 0.f, q = 0.f;
#pragma unroll
        for (int j = 0; j < 8; j++) { s += acc[i][j]; q += acc[i][j]*acc[i][j]; }
        atomicAdd(&ssum[o0+i], s);
        atomicAdd(&ssq [o0+i], q);
    }
    __syncthreads();
    if (tid < 64) {
        atomicAdd(&g_sum[128 + tid], (double)ssum[tid]);
        atomicAdd(&g_sq [128 + tid], (double)ssq[tid]);
    }
}

// ---------------- conv3: bnrelu(y2) -> 128x128x64 GEMM + per-centroid max/min ----------------
__global__ __launch_bounds__(256) void conv3_kernel(const float* __restrict__ bias) {
    __shared__ float fs[64*128];
    __shared__ float ws[16*128];
    __shared__ float scs[64], shs[64];
    __shared__ float ssum[128], ssq[128];
    __shared__ unsigned smx[4*128], smn[4*128];
    int blk = blockIdx.x, tid = threadIdx.x;
    if (tid < 64) { scs[tid] = g_scale[128+tid]; shs[tid] = g_shift[128+tid]; }
    if (tid < 128) { ssum[tid] = 0.f; ssq[tid] = 0.f; }
#pragma unroll
    for (int r = 0; r < 2; r++) { smx[r*256+tid] = 0u; smn[r*256+tid] = 0xFFFFFFFFu; }
    float rw[8];
#pragma unroll
    for (int r = 0; r < 8; r++) rw[r] = g_wt3[r*256 + tid];
    __syncthreads();
    {
        int n = tid & 127, half = (tid >> 7) * 32;
        const float4* yp = (const float4*)(g_y2 + ((size_t)blk*128 + n)*64 + half);
#pragma unroll
        for (int c4 = 0; c4 < 8; c4++) {
            float4 v = yp[c4];
            int c = half + c4*4;
            fs[(c+0)*128+n] = fmaxf(v.x*scs[c+0]+shs[c+0], 0.f);
            fs[(c+1)*128+n] = fmaxf(v.y*scs[c+1]+shs[c+1], 0.f);
            fs[(c+2)*128+n] = fmaxf(v.z*scs[c+2]+shs[c+2], 0.f);
            fs[(c+3)*128+n] = fmaxf(v.w*scs[c+3]+shs[c+3], 0.f);
        }
    }
    int ty = tid & 15, tx = tid >> 4;
    int o0 = ty*8, n0 = tx*8;
    float acc[8][8];
#pragma unroll
    for (int i = 0; i < 8; i++) {
        float bv = bias[o0 + i];
#pragma unroll
        for (int j = 0; j < 8; j++) acc[i][j] = bv;
    }
    __syncthreads();

    for (int kc = 0; kc < 4; kc++) {
#pragma unroll
        for (int r = 0; r < 8; r++) ws[r*256 + tid] = rw[r];
        __syncthreads();
        if (kc < 3) {
#pragma unroll
            for (int r = 0; r < 8; r++) rw[r] = g_wt3[(kc+1)*2048 + r*256 + tid];
        }
#pragma unroll
        for (int kk = 0; kk < 16; kk++) {
            const float4* ap = (const float4*)&ws[kk*128 + o0];
            const float4* bp = (const float4*)&fs[(kc*16 + kk)*128 + n0];
            float4 a0 = ap[0], a1 = ap[1];
            float4 b0 = bp[0], b1 = bp[1];
            float a[8] = {a0.x,a0.y,a0.z,a0.w,a1.x,a1.y,a1.z,a1.w};
            float b[8] = {b0.x,b0.y,b0.z,b0.w,b1.x,b1.y,b1.z,b1.w};
#pragma unroll
            for (int i = 0; i < 8; i++)
#pragma unroll
                for (int j = 0; j < 8; j++)
                    acc[i][j] += a[i]*b[j];
        }
        __syncthreads();
    }

    int cent = tx >> 2;   // thread's 8 samples live in one centroid
#pragma unroll
    for (int i = 0; i < 8; i++) {
        float s = 0.f, q = 0.f, mx = -3.4e38f, mn = 3.4e38f;
#pragma unroll
        for (int j = 0; j < 8; j++) {
            float v = acc[i][j];
            s += v; q += v*v; mx = fmaxf(mx, v); mn = fminf(mn, v);
        }
        atomicAdd(&ssum[o0+i], s);
        atomicAdd(&ssq [o0+i], q);
        atomicMax(&smx[cent*128 + o0+i], fenc(mx));
        atomicMin(&smn[cent*128 + o0+i], fenc(mn));
    }
    __syncthreads();
    if (tid < 128) {
        atomicAdd(&g_sum[256 + tid], (double)ssum[tid]);
        atomicAdd(&g_sq [256 + tid], (double)ssq[tid]);
    }
#pragma unroll
    for (int r = 0; r < 2; r++) {
        int i = r*256 + tid;
        int c = i >> 7, o = i & 127;
        size_t gi = ((size_t)(blk*4 + c))*128 + o;
        g_mx[gi] = fdec(smx[i]);
        g_mn[gi] = fdec(smn[i]);
    }
}

// ---------------- BN finalize ----------------
__global__ void finalize_kernel(const float* __restrict__ g,
                                const float* __restrict__ beta,
                                int layer, int C) {
    int c = threadIdx.x;
    if (c < C) {
        double mean = g_sum[layer*128 + c] / (double)M_TOT;
        double var  = g_sq [layer*128 + c] / (double)M_TOT - mean*mean;
        float rstd = rsqrtf((float)var + 1e-5f);
        float sc = g[c] * rstd;
        g_scale[layer*128 + c] = sc;
        g_shift[layer*128 + c] = beta[c] - (float)mean * sc;
    }
}

// ---------------- final: BN3 fold + relu + (pre-reduced) max ----------------
__global__ __launch_bounds__(128) void final_kernel(float* __restrict__ out) {
    int m = blockIdx.x, o = threadIdx.x;
    float sc = g_scale[256 + o], sh = g_shift[256 + o];
    size_t gi = (size_t)m*128 + o;
    float y = (sc >= 0.f) ? g_mx[gi] : g_mn[gi];
    out[OUT_XYZ_ELEMS + gi] = fmaxf(y*sc + sh, 0.f);
}

extern "C" void kernel_launch(void* const* d_in, const int* in_sizes, int n_in,
                              void* d_out, int out_size) {
    const float* xyz   = (const float*)d_in[0];
    const float* pts   = (const float*)d_in[1];
    const float* w1    = (const float*)d_in[2];
    const float* b1    = (const float*)d_in[3];
    const float* g1    = (const float*)d_in[4];
    const float* beta1 = (const float*)d_in[5];
    const float* w2    = (const float*)d_in[6];
    const float* b2    = (const float*)d_in[7];
    const float* g2    = (const float*)d_in[8];
    const float* beta2 = (const float*)d_in[9];
    const float* w3    = (const float*)d_in[10];
    const float* b3    = (const float*)d_in[11];
    const float* g3    = (const float*)d_in[12];
    const float* beta3 = (const float*)d_in[13];
    float* out = (float*)d_out;

    prep_kernel<<<(B_*N_ + 255)/256, 256>>>(xyz);
    wprep_kernel<<<32, 256>>>(w1, w2, w3);
    fps_kernel<<<B_, 256>>>(out);
    ballq_kernel<<<NC/128, 128>>>();
    conv1_kernel<<<NC/4, 128>>>(pts, b1);
    finalize_kernel<<<1, 128>>>(g1, beta1, 0, 64);
    conv2_kernel<<<NC/4, 128>>>(b2);
    finalize_kernel<<<1, 128>>>(g2, beta2, 1, 64);
    conv3_kernel<<<NC/4, 256>>>(b3);
    finalize_kernel<<<1, 128>>>(g3, beta3, 2, 128);
    final_kernel<<<NC, 128>>>(out);
}